// round 10
// baseline (speedup 1.0000x reference)
#include <cuda_runtime.h>

#define NB    2
#define NE    8
#define NPX   4096      // 64*64
#define KTOP  700
#define NG    4
#define NCH   36        // (NE+1)*NG
#define OUTW  256
#define NPROD 128       // producer blocks (chunks) per batch

__device__ int g_topk_idx[NB * KTOP];
__device__ int g_done[NB];      // producers finished per batch (reset at end)
__device__ int g_alldone;       // block-retirement counter (reset at end)

__device__ __forceinline__ float frcp(float x) {
    float r;
    asm("rcp.approx.f32 %0, %1;" : "=f"(r) : "f"(x));
    return r;
}

// ---------------------------------------------------------------------------
// Single fused kernel, grid (KTOP, NB), 256 threads.
//
// Stage A (blocks with linear bid < NB*NPROD only): exact top-k by rank
// counting. Producer block c of batch pb caches all 4096 monotonic u32 keys
// in SMEM (reusing low[]), each of its 32 elements gets its rank counted by
// 8 lanes over interleaved slices + shuffle reduce; rank<700 scatters the
// index (and sigmoid score) directly into sorted position. Producers bump
// g_done[pb] when finished. All producers sit in wave 1 (bids 0..255), so
// spin-waiting consumers cannot starve them.
//
// Stage B (all blocks): spin (tid0, __nanosleep) until g_done[b]==NPROD,
// read own top-k index via __ldcg, gather 36 weights, compute the 64x64
// group-product mask into SMEM, then COLUMN-WALK bilinear 4x upsample:
// thread = (float4-column, row-quarter); rolling 3-tap register window in y
// needs only 3 LDS per 4 STG.128 (vs 24 before) -> L1 wavefronts ~halved so
// the DRAM write stream, not L1tex, becomes the limiter.
//
// Last retiring block resets g_done/g_alldone so graph replays are clean.
// ---------------------------------------------------------------------------
__global__ __launch_bounds__(256, 6)
void fused_kernel(const float* __restrict__ obj,   // (NB, 1, 64, 64)
                  const float* __restrict__ enc,   // (NB, NE, 64, 64)
                  const float* __restrict__ wts,   // (NB, NCH, 64, 64)
                  float* __restrict__ out,         // (NB, KTOP, 256, 256)
                  float* __restrict__ scores) {    // (NB, KTOP)
    __shared__ float low[NPX];      // keys (stage A) then low-res mask (B)
    __shared__ float swt[NCH];

    const int k   = blockIdx.x;
    const int b   = blockIdx.y;
    const int tid = threadIdx.x;
    const int lb  = b * KTOP + k;   // linear bid (x fastest)

    // ---------------- Stage A: producer duty ----------------
    if (lb < NB * NPROD) {
        const int pb = lb >> 7;             // batch this producer serves
        const int c  = lb & (NPROD - 1);    // 32-element chunk
        unsigned* key = (unsigned*)low;
        const float* p = obj + pb * NPX;

        for (int i = tid; i < NPX; i += 256) {
            unsigned u = __float_as_uint(p[i]);
            key[i] = u ^ (unsigned)(((int)u >> 31) | 0x80000000);
        }
        __syncthreads();

        const int e = c * 32 + (tid >> 3);
        const int s = tid & 7;
        const unsigned me = key[e];
        int cnt = 0;
#pragma unroll 8
        for (int t = 0; t < 512; t++) {
            const int i = s + (t << 3);
            const unsigned ki = key[i];
            cnt += (ki > me) || (ki == me && i < e);
        }
        cnt += __shfl_down_sync(0xffffffffu, cnt, 4);
        cnt += __shfl_down_sync(0xffffffffu, cnt, 2);
        cnt += __shfl_down_sync(0xffffffffu, cnt, 1);

        if (s == 0 && cnt < KTOP) {
            scores[pb * KTOP + cnt] = frcp(1.0f + __expf(-p[e]));
            g_topk_idx[pb * KTOP + cnt] = e;
        }
        __threadfence();                 // publish scatters device-wide
        __syncthreads();                 // whole block's scatters ordered
        if (tid == 0) atomicAdd(&g_done[pb], 1);
        __syncthreads();                 // key[] reads done -> low reusable
    }

    // ---------------- wait for my batch's top-k ----------------
    if (tid == 0) {
        while (((volatile int*)g_done)[b] < NPROD) __nanosleep(64);
    }
    __syncthreads();

    const int pos = __ldcg(&g_topk_idx[b * KTOP + k]);   // L2-coherent read
    if (tid < NCH) swt[tid] = wts[(b * NCH + tid) * NPX + pos];
    __syncthreads();

    // ---------------- compute 64x64 group-product mask ----------------
    const volatile float* vw = swt;     // keep weights in LDS, regs low
    const float2* encb = (const float2*)(enc + b * NE * NPX);

#pragma unroll
    for (int it = 0; it < 8; it++) {
        const int q = it * 256 + tid;   // float2 index in 64x64 plane
        float2 ev[NE];
#pragma unroll
        for (int e = 0; e < NE; e++)
            ev[e] = __ldg(encb + e * (NPX / 2) + q);

        float px = 1.f, py = 1.f;
#pragma unroll
        for (int g = 0; g < NG; g++) {
            float ax = vw[g * (NE + 1) + NE];
            float ay = ax;
#pragma unroll
            for (int e = 0; e < NE; e++) {
                const float w = vw[g * (NE + 1) + e];
                ax = fmaf(w, ev[e].x, ax);
                ay = fmaf(w, ev[e].y, ay);
            }
            px *= 1.f + __expf(-ax);
            py *= 1.f + __expf(-ay);
        }
        ((float2*)low)[q] = make_float2(frcp(px), frcp(py));
    }
    __syncthreads();

    // ---------------- column-walk 4x bilinear upsample ----------------
    // thread -> float4-column j (= tid&63) and row-quarter (= tid>>6).
    // Output rows 4m+p use input rows (m-1,m) for p=0,1 (fy 0.625, 0.875)
    // and (m,m+1) for p=2,3 (fy 0.125, 0.375); clamped rows collapse to the
    // edge row, matching jax half-pixel bilinear exactly.
    {
        const int j  = tid & 63;
        const int q4 = tid >> 6;
        const int jp = (j == 0)  ? 0  : j - 1;
        const int jn = (j == 63) ? 63 : j + 1;
        const int m0 = q4 * 16;

        float* orow = out + ((size_t)(b * KTOP + k)) * (OUTW * OUTW)
                          + (q4 * 64) * OUTW + j * 4;

        float ap, ac, an, bp, bc, bn;
        {
            const float* r = low + ((m0 == 0) ? 0 : m0 - 1) * 64;
            ap = r[jp]; ac = r[j]; an = r[jn];
            const float* rb = low + m0 * 64;
            bp = rb[jp]; bc = rb[j]; bn = rb[jn];
        }

#pragma unroll 1
        for (int m = m0; m < m0 + 16; m++) {
            const int mn = (m >= 63) ? 63 : m + 1;
            const float* rc = low + mn * 64;
            const float cp = rc[jp], cc = rc[j], cn = rc[jn];

#pragma unroll
            for (int p = 0; p < 4; p++) {
                const float fy = (p == 0) ? 0.625f : (p == 1) ? 0.875f
                               : (p == 2) ? 0.125f : 0.375f;
                float vp, vc, vn;
                if (p < 2) {
                    vp = fmaf(fy, bp - ap, ap);
                    vc = fmaf(fy, bc - ac, ac);
                    vn = fmaf(fy, bn - an, an);
                } else {
                    vp = fmaf(fy, cp - bp, bp);
                    vc = fmaf(fy, cc - bc, bc);
                    vn = fmaf(fy, cn - bn, bn);
                }
                const float dp = vp - vc, dn = vn - vc;
                float4 o;
                o.x = fmaf(0.375f, dp, vc);
                o.y = fmaf(0.125f, dp, vc);
                o.z = fmaf(0.125f, dn, vc);
                o.w = fmaf(0.375f, dn, vc);
                __stcs((float4*)(orow + p * OUTW), o);
            }
            ap = bp; ac = bc; an = bn;
            bp = cp; bc = cc; bn = cn;
            orow += 4 * OUTW;
        }
    }

    // ---------------- reset flags for next graph replay ----------------
    __syncthreads();
    if (tid == 0) {
        __threadfence();
        if (atomicAdd(&g_alldone, 1) == NB * KTOP - 1) {
            g_done[0] = 0;
            g_done[1] = 0;
            __threadfence();
            g_alldone = 0;
        }
    }
}

// ---------------------------------------------------------------------------
extern "C" void kernel_launch(void* const* d_in, const int* in_sizes, int n_in,
                              void* d_out, int out_size) {
    const float* obj = (const float*)d_in[0];  // objectness_logits (2,1,64,64)
    const float* enc = (const float*)d_in[1];  // mask_encodings   (2,8,64,64)
    const float* wts = (const float*)d_in[2];  // weights          (2,36,64,64)
    float* out    = (float*)d_out;             // m (2,700,256,256) then scores
    float* scores = out + (size_t)NB * KTOP * OUTW * OUTW;

    dim3 grid(KTOP, NB);
    fused_kernel<<<grid, 256>>>(obj, enc, wts, out, scores);
}

// round 11
// speedup vs baseline: 1.1084x; 1.1084x over previous
#include <cuda_runtime.h>

#define NB   2
#define NE   8
#define NPX  4096      // 64*64
#define KTOP 700
#define NG   4
#define NCH  36        // (NE+1)*NG
#define OUTW 256

__device__ int g_topk_idx[NB * KTOP];

__device__ __forceinline__ float frcp(float x) {
    float r;
    asm("rcp.approx.f32 %0, %1;" : "=f"(r) : "f"(x));
    return r;
}

// ---------------------------------------------------------------------------
// Kernel 1: exact top-k by HISTOGRAM-PRUNED rank counting.
// Every block caches all 4096 monotonic u32 keys in SMEM, builds a 256-bin
// histogram of the top byte, and suffix-scans it to find the exact bin T* of
// the 700th-largest key. Only elements with bin >= T* (~700-900 of 4096) get
// a full rank count (#{i : key_i > key_e, ties by index}), ~9x less SMEM
// traffic than ranking everything. rank < 700 scatters index + sigmoid score
// directly into sorted position (ranks are unique -> no collisions).
// Grid (128, NB) x 256: block owns 32 elements; its 8 warps grab candidates
// round-robin, each lane scans a contiguous 32-stride slice (conflict-free).
// ---------------------------------------------------------------------------
__global__ __launch_bounds__(256)
void topk_kernel(const float* __restrict__ obj,
                 float* __restrict__ scores) {
    __shared__ unsigned key[NPX];     // 16 KB
    __shared__ int hist[256];
    __shared__ int thr_bin;
    const int b    = blockIdx.y;
    const int tid  = threadIdx.x;
    const int base = blockIdx.x * 32;
    const float* p = obj + b * NPX;

    hist[tid] = 0;
    __syncthreads();
    for (int i = tid; i < NPX; i += 256) {
        unsigned u = __float_as_uint(p[i]);
        u ^= (unsigned)(((int)u >> 31) | 0x80000000);   // monotonic map
        key[i] = u;
        atomicAdd(&hist[u >> 24], 1);
    }
    __syncthreads();

    if (tid < 32) {
        int s = 0;
#pragma unroll
        for (int q = 0; q < 8; q++) s += hist[tid * 8 + q];
        int suf = s;                       // inclusive suffix-sum over lanes
#pragma unroll
        for (int d = 1; d < 32; d <<= 1) {
            int o = __shfl_down_sync(0xffffffffu, suf, d);
            if (tid + d < 32) suf += o;
        }
        // lane L = highest lane whose 8-bin group still reaches rank 700
        unsigned m = __ballot_sync(0xffffffffu, suf >= KTOP);
        int L = 31 - __clz(m);
        int sufn = __shfl_down_sync(0xffffffffu, suf, 1);  // suffix of L+1
        if (tid == L) {
            int c = (L == 31) ? 0 : sufn;
            int bb = L * 8 + 7;
            while (c + hist[bb] < KTOP) { c += hist[bb]; bb--; }
            thr_bin = bb;                  // bin containing the 700th key
        }
    }
    __syncthreads();
    const unsigned T = (unsigned)thr_bin;
    const int warp = tid >> 5, lane = tid & 31;

    for (int c = warp; c < 32; c += 8) {
        const int e = base + c;
        const unsigned me = key[e];
        if ((me >> 24) < T) continue;      // cannot be in top-700
        int cnt = 0;
#pragma unroll 4
        for (int t = 0; t < 128; t++) {
            const int i = lane + (t << 5);
            const unsigned ki = key[i];
            cnt += (ki > me) || (ki == me && i < e);
        }
        cnt += __shfl_down_sync(0xffffffffu, cnt, 16);
        cnt += __shfl_down_sync(0xffffffffu, cnt, 8);
        cnt += __shfl_down_sync(0xffffffffu, cnt, 4);
        cnt += __shfl_down_sync(0xffffffffu, cnt, 2);
        cnt += __shfl_down_sync(0xffffffffu, cnt, 1);
        if (lane == 0 && cnt < KTOP) {
            scores[b * KTOP + cnt] = frcp(1.0f + __expf(-p[e]));
            g_topk_idx[b * KTOP + cnt] = e;
        }
    }
}

// ---------------------------------------------------------------------------
// Kernel 2: one block per (b, k). Gather 36 weights at the selected position,
// compute the 64x64 group-product mask into SMEM
//   mask = 1 / prod_g (1 + exp(-(w_g . enc + b_g)))
// then COLUMN-WALK 4x bilinear upsample: thread = (float4-column, row
// quarter); rolling 3-tap register window in y -> 3 LDS per 4 STG.128
// (vs 24 for the row-warp scheme), removing the L1tex limiter on the
// 367 MB store stream. Math validated in R9 (rel_err 1.16e-7).
// ---------------------------------------------------------------------------
__global__ __launch_bounds__(256, 6)
void mask_kernel(const float* __restrict__ enc,   // (NB, NE, 64, 64)
                 const float* __restrict__ wts,   // (NB, NCH, 64, 64)
                 float* __restrict__ out) {       // (NB, KTOP, 256, 256)
    __shared__ float low[NPX];
    __shared__ float swt[NCH];

    const int k   = blockIdx.x;
    const int b   = blockIdx.y;
    const int tid = threadIdx.x;

    const int pos = g_topk_idx[b * KTOP + k];
    if (tid < NCH) swt[tid] = wts[(b * NCH + tid) * NPX + pos];
    __syncthreads();

    const volatile float* vw = swt;     // keep weights in LDS, regs low
    const float2* encb = (const float2*)(enc + b * NE * NPX);

#pragma unroll
    for (int it = 0; it < 8; it++) {
        const int q = it * 256 + tid;   // float2 index in 64x64 plane
        float2 ev[NE];
#pragma unroll
        for (int e = 0; e < NE; e++)
            ev[e] = __ldg(encb + e * (NPX / 2) + q);

        float px = 1.f, py = 1.f;
#pragma unroll
        for (int g = 0; g < NG; g++) {
            float ax = vw[g * (NE + 1) + NE];
            float ay = ax;
#pragma unroll
            for (int e = 0; e < NE; e++) {
                const float w = vw[g * (NE + 1) + e];
                ax = fmaf(w, ev[e].x, ax);
                ay = fmaf(w, ev[e].y, ay);
            }
            px *= 1.f + __expf(-ax);
            py *= 1.f + __expf(-ay);
        }
        ((float2*)low)[q] = make_float2(frcp(px), frcp(py));
    }
    __syncthreads();

    // Column-walk upsample: output rows 4m+p take input rows (m-1,m) for
    // p=0,1 (fy 0.625, 0.875) and (m,m+1) for p=2,3 (fy 0.125, 0.375);
    // clamps collapse to the edge row, matching jax half-pixel bilinear.
    {
        const int j  = tid & 63;        // float4 column
        const int q4 = tid >> 6;        // row quarter
        const int jp = (j == 0)  ? 0  : j - 1;
        const int jn = (j == 63) ? 63 : j + 1;
        const int m0 = q4 * 16;

        float* orow = out + ((size_t)(b * KTOP + k)) * (OUTW * OUTW)
                          + (q4 * 64) * OUTW + j * 4;

        float ap, ac, an, bp, bc, bn;
        {
            const float* ra = low + ((m0 == 0) ? 0 : m0 - 1) * 64;
            ap = ra[jp]; ac = ra[j]; an = ra[jn];
            const float* rb = low + m0 * 64;
            bp = rb[jp]; bc = rb[j]; bn = rb[jn];
        }

#pragma unroll 1
        for (int m = m0; m < m0 + 16; m++) {
            const int mn = (m >= 63) ? 63 : m + 1;
            const float* rc = low + mn * 64;
            const float cp = rc[jp], cc = rc[j], cn = rc[jn];

#pragma unroll
            for (int p = 0; p < 4; p++) {
                const float fy = (p == 0) ? 0.625f : (p == 1) ? 0.875f
                               : (p == 2) ? 0.125f : 0.375f;
                float vp, vc, vn;
                if (p < 2) {
                    vp = fmaf(fy, bp - ap, ap);
                    vc = fmaf(fy, bc - ac, ac);
                    vn = fmaf(fy, bn - an, an);
                } else {
                    vp = fmaf(fy, cp - bp, bp);
                    vc = fmaf(fy, cc - bc, bc);
                    vn = fmaf(fy, cn - bn, bn);
                }
                const float dp = vp - vc, dn = vn - vc;
                float4 o;
                o.x = fmaf(0.375f, dp, vc);
                o.y = fmaf(0.125f, dp, vc);
                o.z = fmaf(0.125f, dn, vc);
                o.w = fmaf(0.375f, dn, vc);
                __stcs((float4*)(orow + p * OUTW), o);
            }
            ap = bp; ac = bc; an = bn;
            bp = cp; bc = cc; bn = cn;
            orow += 4 * OUTW;
        }
    }
}

// ---------------------------------------------------------------------------
extern "C" void kernel_launch(void* const* d_in, const int* in_sizes, int n_in,
                              void* d_out, int out_size) {
    const float* obj = (const float*)d_in[0];  // objectness_logits (2,1,64,64)
    const float* enc = (const float*)d_in[1];  // mask_encodings   (2,8,64,64)
    const float* wts = (const float*)d_in[2];  // weights          (2,36,64,64)
    float* out    = (float*)d_out;             // m (2,700,256,256) then scores
    float* scores = out + (size_t)NB * KTOP * OUTW * OUTW;

    dim3 tg(128, NB);
    topk_kernel<<<tg, 256>>>(obj, scores);
    dim3 grid(KTOP, NB);
    mask_kernel<<<grid, 256>>>(enc, wts, out);
}